// round 2
// baseline (speedup 1.0000x reference)
#include <cuda_runtime.h>
#include <cuda_bf16.h>
#include <cstdint>

#define EMB 128
#define PRED_IN 532
#define MAX_NODES 131072
#define MAX_REL 1024
#define NPB 8   // nodes per block in table kernel

// ---------------- scratch (static device globals; no allocation) ----------------
__device__ __align__(16) float g_A[MAX_NODES * EMB];      // W1_h . h_e_full[n]
__device__ __align__(16) float g_B[MAX_NODES * EMB];      // W1_t . h_e_full[n]
__device__ __align__(16) float g_Rm[MAX_REL * EMB];       // b1 + W1_q.q + W1_r.rel[r]
__device__ __align__(16) float g_WTq[EMB * EMB];          // [k][i] = W1[i][k]
__device__ __align__(16) float g_WThA[EMB * EMB];         // [k][i] = W1[i][128+k]
__device__ __align__(16) float g_WTr[EMB * EMB];          // [k][i] = W1[i][266+k]
__device__ __align__(16) float g_WThB[EMB * EMB];         // [k][i] = W1[i][394+k]
__device__ __align__(16) float g_WTpA[10 * EMB];          // [j][i] = W1[i][256+j]
__device__ __align__(16) float g_WTpB[10 * EMB];          // [j][i] = W1[i][522+j]
__device__ float g_deg_t[MAX_NODES];
__device__ float g_deg_h[MAX_NODES];
__device__ __align__(16) float2 g_scr[MAX_NODES];
__device__ __align__(16) float2 g_d[4][MAX_NODES];        // d1,d2 (fwd) d3,d4 (rev)

// ---------------- kernels ----------------

__global__ void k_init(int n_nodes) {
    int i = blockIdx.x * blockDim.x + threadIdx.x;
    if (i < n_nodes) {
        g_deg_t[i] = 0.f;
        g_deg_h[i] = 0.f;
        g_scr[i] = make_float2(0.f, 0.f);
    }
}

__global__ void k_degree(const int* __restrict__ h_id, const int* __restrict__ t_id, int E) {
    int e = blockIdx.x * blockDim.x + threadIdx.x;
    if (e < E) {
        atomicAdd(&g_deg_t[t_id[e]], 1.f);
        atomicAdd(&g_deg_h[h_id[e]], 1.f);
    }
}

// Transpose the W1 column-blocks into [k][i] layouts for coalesced GEMM reads.
__global__ void k_prep(const float* __restrict__ W1) {
    int idx = blockIdx.x * blockDim.x + threadIdx.x;
    if (idx < EMB * EMB) {
        int k = idx >> 7;          // 0..127
        int i = idx & 127;
        const float* row = W1 + i * PRED_IN;
        g_WTq[idx]  = row[k];
        g_WThA[idx] = row[128 + k];
        g_WTr[idx]  = row[266 + k];
        g_WThB[idx] = row[394 + k];
    }
    if (idx < 10 * EMB) {
        int j = idx >> 7;          // 0..9
        int i = idx & 127;
        const float* row = W1 + i * PRED_IN;
        g_WTpA[idx] = row[256 + j];
        g_WTpB[idx] = row[522 + j];
    }
}

// Rm[r][i] = b1[i] + dot(W1[i,0:128], q) + dot(W1[i,266:394], rel[r])
__global__ void k_rm(const float* __restrict__ q, const float* __restrict__ rel,
                     const float* __restrict__ b1, int n_rel) {
    __shared__ float qs[EMB];
    __shared__ float rs[EMB];
    int i = threadIdx.x;
    int r = blockIdx.x;
    qs[i] = q[i];
    rs[i] = rel[r * EMB + i];
    __syncthreads();
    float acc = b1[i];
    #pragma unroll 4
    for (int k = 0; k < EMB; k++) {
        acc += g_WTq[k * EMB + i] * qs[k];
        acc += g_WTr[k * EMB + i] * rs[k];
    }
    g_Rm[r * EMB + i] = acc;
}

// scatter-add: g_scr[dst[e]] += x[src[e]]   (float2 reduction)
// src_round < 0 -> x = topic; else x = g_d[src_round]  (device-side symbol access ONLY)
__global__ void k_scatter(const float2* __restrict__ topic, int src_round,
                          const int* __restrict__ src, const int* __restrict__ dst, int E) {
    int e = blockIdx.x * blockDim.x + threadIdx.x;
    if (e < E) {
        const float2* x = (src_round < 0) ? topic : g_d[src_round];
        float2 v = x[src[e]];
        float2* p = &g_scr[dst[e]];
        asm volatile("red.global.add.v2.f32 [%0], {%1, %2};"
                     :: "l"(p), "f"(v.x), "f"(v.y) : "memory");
    }
}

// g_d[out_round][i] = scr[i]/max(deg[i],1);  scr[i]=0 (ready for next round)
__global__ void k_norm(int out_round, int use_h_deg, int n_nodes) {
    int i = blockIdx.x * blockDim.x + threadIdx.x;
    if (i < n_nodes) {
        float2 s = g_scr[i];
        float c = fmaxf(use_h_deg ? g_deg_h[i] : g_deg_t[i], 1.f);
        g_d[out_round][i] = make_float2(s.x / c, s.y / c);
        g_scr[i] = make_float2(0.f, 0.f);
    }
}

// Node tables: A[n][i], B[n][i]. 128 threads/block, NPB nodes/block.
__global__ __launch_bounds__(EMB) void k_tables(
    const float* __restrict__ ent, const float* __restrict__ nte,
    const float* __restrict__ topic, int n_text, int n_nodes) {
    __shared__ float he_s[EMB * NPB];   // [k*NPB + n]  (16B aligned chunks of 8)
    __shared__ float pe_s[NPB * 10];    // [n*10 + j]
    int tid = threadIdx.x;
    int base = blockIdx.x * NPB;

    #pragma unroll
    for (int n = 0; n < NPB; n++) {
        int id = base + n;
        float v = 0.f;
        if (id < n_nodes) v = (id < n_text) ? ent[id * EMB + tid] : nte[tid];
        he_s[tid * NPB + n] = v;
    }
    if (tid < NPB * 10) {
        int n = tid / 10, j = tid % 10;
        int id = base + n;
        float v = 0.f;
        if (id < n_nodes) {
            if (j < 2) v = topic[id * 2 + j];
            else {
                int rr = (j - 2) >> 1;
                float2 d = g_d[rr][id];
                v = (j & 1) ? d.y : d.x;
            }
        }
        pe_s[tid] = v;
    }
    __syncthreads();

    float accA[NPB], accB[NPB];
    #pragma unroll
    for (int n = 0; n < NPB; n++) { accA[n] = 0.f; accB[n] = 0.f; }

    #pragma unroll 2
    for (int k = 0; k < EMB; k++) {
        float wa = g_WThA[k * EMB + tid];
        float wb = g_WThB[k * EMB + tid];
        float4 h0 = *(const float4*)&he_s[k * NPB];
        float4 h1 = *(const float4*)&he_s[k * NPB + 4];
        float hv[NPB] = {h0.x, h0.y, h0.z, h0.w, h1.x, h1.y, h1.z, h1.w};
        #pragma unroll
        for (int n = 0; n < NPB; n++) {
            accA[n] += wa * hv[n];
            accB[n] += wb * hv[n];
        }
    }
    #pragma unroll
    for (int j = 0; j < 10; j++) {
        float wa = g_WTpA[j * EMB + tid];
        float wb = g_WTpB[j * EMB + tid];
        #pragma unroll
        for (int n = 0; n < NPB; n++) {
            float pv = pe_s[n * 10 + j];
            accA[n] += wa * pv;
            accB[n] += wb * pv;
        }
    }
    #pragma unroll
    for (int n = 0; n < NPB; n++) {
        int id = base + n;
        if (id < n_nodes) {
            g_A[id * EMB + tid] = accA[n];
            g_B[id * EMB + tid] = accB[n];
        }
    }
}

// Edge combine: warp per edge. pred[e] = b2 + W2 . relu(A[h] + Rm[r] + B[t])
__global__ __launch_bounds__(256) void k_edge(
    const int* __restrict__ h_id, const int* __restrict__ r_id, const int* __restrict__ t_id,
    const float* __restrict__ W2, const float* __restrict__ b2,
    float* __restrict__ out, int E) {
    int gw = (blockIdx.x * blockDim.x + threadIdx.x) >> 5;
    int lane = threadIdx.x & 31;
    if (gw >= E) return;
    int h = h_id[gw];
    int t = t_id[gw];
    int r = r_id[gw];
    const float4* A4 = (const float4*)g_A;
    const float4* B4 = (const float4*)g_B;
    const float4* R4 = (const float4*)g_Rm;
    float4 a = A4[h * 32 + lane];
    float4 b = B4[t * 32 + lane];
    float4 c = R4[r * 32 + lane];
    float4 w = ((const float4*)W2)[lane];
    float s = w.x * fmaxf(a.x + b.x + c.x, 0.f)
            + w.y * fmaxf(a.y + b.y + c.y, 0.f)
            + w.z * fmaxf(a.z + b.z + c.z, 0.f)
            + w.w * fmaxf(a.w + b.w + c.w, 0.f);
    #pragma unroll
    for (int off = 16; off; off >>= 1) s += __shfl_xor_sync(0xFFFFFFFFu, s, off);
    if (lane == 0) out[gw] = s + b2[0];
}

// ---------------- launch ----------------

extern "C" void kernel_launch(void* const* d_in, const int* in_sizes, int n_in,
                              void* d_out, int out_size) {
    const int*   h_id  = (const int*)d_in[0];
    const int*   r_id  = (const int*)d_in[1];
    const int*   t_id  = (const int*)d_in[2];
    const float* q     = (const float*)d_in[3];
    const float* ent   = (const float*)d_in[4];
    // d_in[5] = num_non_text_entities (scalar) — derived from topic shape instead
    const float* rel   = (const float*)d_in[6];
    const float* topic = (const float*)d_in[7];
    const float* nte   = (const float*)d_in[8];
    const float* W1    = (const float*)d_in[9];
    const float* b1    = (const float*)d_in[10];
    const float* W2    = (const float*)d_in[11];
    const float* b2    = (const float*)d_in[12];
    float* out = (float*)d_out;

    int E       = in_sizes[0];
    int n_text  = in_sizes[4] / EMB;
    int n_rel   = in_sizes[6] / EMB;
    int n_nodes = in_sizes[7] / 2;

    const int T = 256;
    int nb_nodes = (n_nodes + T - 1) / T;
    int nb_edges = (E + T - 1) / T;

    k_init<<<nb_nodes, T>>>(n_nodes);
    k_degree<<<nb_edges, T>>>(h_id, t_id, E);
    k_prep<<<(EMB * EMB + T - 1) / T, T>>>(W1);
    k_rm<<<n_rel, EMB>>>(q, rel, b1, n_rel);

    const float2* topic2 = (const float2*)topic;
    // forward rounds (h -> t, deg by t)
    k_scatter<<<nb_edges, T>>>(topic2, -1, h_id, t_id, E);
    k_norm<<<nb_nodes, T>>>(0, 0, n_nodes);
    k_scatter<<<nb_edges, T>>>(topic2, 0, h_id, t_id, E);
    k_norm<<<nb_nodes, T>>>(1, 0, n_nodes);
    // reverse rounds (t -> h, deg by h)
    k_scatter<<<nb_edges, T>>>(topic2, -1, t_id, h_id, E);
    k_norm<<<nb_nodes, T>>>(2, 1, n_nodes);
    k_scatter<<<nb_edges, T>>>(topic2, 2, t_id, h_id, E);
    k_norm<<<nb_nodes, T>>>(3, 1, n_nodes);

    k_tables<<<(n_nodes + NPB - 1) / NPB, EMB>>>(ent, nte, topic, n_text, n_nodes);

    int nb_e = (E + 7) / 8;  // 8 warps per 256-thread block, warp per edge
    k_edge<<<nb_e, T>>>(h_id, r_id, t_id, W2, b2, out, E);
}

// round 3
// speedup vs baseline: 1.1023x; 1.1023x over previous
#include <cuda_runtime.h>
#include <cuda_bf16.h>
#include <cstdint>

#define EMB 128
#define PRED_IN 532
#define MAX_NODES 131072
#define MAX_REL 1024
#define NPB 32    // nodes per block in table kernel (16 float2 pairs)
#define RPB 8     // relations per block in k_rm

// ---------------- scratch (static device globals; no allocation) ----------------
__device__ __align__(16) float g_A[MAX_NODES * EMB];
__device__ __align__(16) float g_B[MAX_NODES * EMB];
__device__ __align__(16) float g_Rm[MAX_REL * EMB];
__device__ __align__(16) float g_WTq[EMB * EMB];          // [k][i] = W1[i][k]
__device__ __align__(16) float g_WThA[EMB * EMB];         // [k][i] = W1[i][128+k]
__device__ __align__(16) float g_WTr[EMB * EMB];          // [k][i] = W1[i][266+k]
__device__ __align__(16) float g_WThB[EMB * EMB];         // [k][i] = W1[i][394+k]
__device__ __align__(16) float g_WTpA[10 * EMB];          // [j][i] = W1[i][256+j]
__device__ __align__(16) float g_WTpB[10 * EMB];          // [j][i] = W1[i][522+j]
__device__ float g_deg_t[MAX_NODES];
__device__ float g_deg_h[MAX_NODES];
__device__ __align__(16) float2 g_scrf[MAX_NODES];
__device__ __align__(16) float2 g_scrr[MAX_NODES];
__device__ __align__(16) float2 g_d[4][MAX_NODES];        // d0,d1 fwd; d2,d3 rev

// ---------------- f32x2 helpers ----------------
__device__ __forceinline__ unsigned long long pack2(float a, float b) {
    unsigned long long r;
    asm("mov.b64 %0, {%1, %2};" : "=l"(r) : "f"(a), "f"(b));
    return r;
}
__device__ __forceinline__ void unpack2(unsigned long long v, float& lo, float& hi) {
    asm("mov.b64 {%0, %1}, %2;" : "=f"(lo), "=f"(hi) : "l"(v));
}
__device__ __forceinline__ void ffma2(unsigned long long& acc, unsigned long long a,
                                      unsigned long long b) {
    asm("fma.rn.f32x2 %0, %1, %2, %0;" : "+l"(acc) : "l"(a), "l"(b));
}

// ---------------- kernels ----------------

__global__ void k_init(int n_nodes) {
    int i = blockIdx.x * blockDim.x + threadIdx.x;
    if (i < n_nodes) {
        g_deg_t[i] = 0.f;
        g_deg_h[i] = 0.f;
        g_scrf[i] = make_float2(0.f, 0.f);
        g_scrr[i] = make_float2(0.f, 0.f);
    }
}

__global__ void k_prep(const float* __restrict__ W1) {
    int idx = blockIdx.x * blockDim.x + threadIdx.x;
    if (idx < EMB * EMB) {
        int k = idx >> 7;
        int i = idx & 127;
        const float* row = W1 + i * PRED_IN;
        g_WTq[idx]  = row[k];
        g_WThA[idx] = row[128 + k];
        g_WTr[idx]  = row[266 + k];
        g_WThB[idx] = row[394 + k];
    }
    if (idx < 10 * EMB) {
        int j = idx >> 7;
        int i = idx & 127;
        const float* row = W1 + i * PRED_IN;
        g_WTpA[idx] = row[256 + j];
        g_WTpB[idx] = row[522 + j];
    }
}

// Rm[r][i] = b1[i] + dot(W1[i,0:128], q) + dot(W1[i,266:394], rel[r]); RPB rels/block
__global__ __launch_bounds__(EMB) void k_rm(const float* __restrict__ q,
                                            const float* __restrict__ rel,
                                            const float* __restrict__ b1, int n_rel) {
    __shared__ float qs[EMB];
    __shared__ float rs[RPB][EMB];
    int i = threadIdx.x;
    int rbase = blockIdx.x * RPB;
    qs[i] = q[i];
    #pragma unroll
    for (int r = 0; r < RPB; r++) {
        int rid = rbase + r;
        rs[r][i] = (rid < n_rel) ? rel[rid * EMB + i] : 0.f;
    }
    __syncthreads();
    float accq = b1[i];
    float acc[RPB];
    #pragma unroll
    for (int r = 0; r < RPB; r++) acc[r] = 0.f;
    #pragma unroll 4
    for (int k = 0; k < EMB; k++) {
        float wq = g_WTq[k * EMB + i];
        float wr = g_WTr[k * EMB + i];
        accq += wq * qs[k];
        #pragma unroll
        for (int r = 0; r < RPB; r++) acc[r] += wr * rs[r][k];
    }
    #pragma unroll
    for (int r = 0; r < RPB; r++) {
        int rid = rbase + r;
        if (rid < n_rel) g_Rm[rid * EMB + i] = accq + acc[r];
    }
}

// Round 1 fused: degrees + fwd scatter (topic[h]->t) + rev scatter (topic[t]->h)
__global__ void k_sc1(const float2* __restrict__ topic, const int* __restrict__ h_id,
                      const int* __restrict__ t_id, int E) {
    int e = blockIdx.x * blockDim.x + threadIdx.x;
    if (e < E) {
        int h = h_id[e];
        int t = t_id[e];
        float2 vh = topic[h];
        float2 vt = topic[t];
        float2* pf = &g_scrf[t];
        float2* pr = &g_scrr[h];
        asm volatile("red.global.add.v2.f32 [%0], {%1, %2};"
                     :: "l"(pf), "f"(vh.x), "f"(vh.y) : "memory");
        asm volatile("red.global.add.v2.f32 [%0], {%1, %2};"
                     :: "l"(pr), "f"(vt.x), "f"(vt.y) : "memory");
        asm volatile("red.global.add.f32 [%0], %1;" :: "l"(&g_deg_t[t]), "f"(1.f) : "memory");
        asm volatile("red.global.add.f32 [%0], %1;" :: "l"(&g_deg_h[h]), "f"(1.f) : "memory");
    }
}

// normalize both directions into g_d[fo]/g_d[ro], zero scratch
__global__ void k_norm2d(int fo, int ro, int n_nodes) {
    int i = blockIdx.x * blockDim.x + threadIdx.x;
    if (i < n_nodes) {
        float2 sf = g_scrf[i];
        float2 sr = g_scrr[i];
        float ct = fmaxf(g_deg_t[i], 1.f);
        float ch = fmaxf(g_deg_h[i], 1.f);
        g_d[fo][i] = make_float2(sf.x / ct, sf.y / ct);
        g_d[ro][i] = make_float2(sr.x / ch, sr.y / ch);
        g_scrf[i] = make_float2(0.f, 0.f);
        g_scrr[i] = make_float2(0.f, 0.f);
    }
}

// Round 2 fused: fwd scatter (d0[h]->t) + rev scatter (d2[t]->h)
__global__ void k_sc2(const int* __restrict__ h_id, const int* __restrict__ t_id, int E) {
    int e = blockIdx.x * blockDim.x + threadIdx.x;
    if (e < E) {
        int h = h_id[e];
        int t = t_id[e];
        float2 vh = g_d[0][h];
        float2 vt = g_d[2][t];
        float2* pf = &g_scrf[t];
        float2* pr = &g_scrr[h];
        asm volatile("red.global.add.v2.f32 [%0], {%1, %2};"
                     :: "l"(pf), "f"(vh.x), "f"(vh.y) : "memory");
        asm volatile("red.global.add.v2.f32 [%0], {%1, %2};"
                     :: "l"(pr), "f"(vt.x), "f"(vt.y) : "memory");
    }
}

// Node tables via packed f32x2: 32 nodes (16 pairs) per 128-thread block.
__global__ __launch_bounds__(EMB) void k_tables(
    const float* __restrict__ ent, const float* __restrict__ nte,
    const float* __restrict__ topic, int n_text, int n_nodes) {
    __shared__ float2 he2[16][EMB];   // [pair][k] = {node 2p, node 2p+1}
    __shared__ float2 pe2[16][10];    // [pair][j]
    int tid = threadIdx.x;
    int base = blockIdx.x * NPB;

    // load h_e (pair-packed): thread tid handles k=tid for all 16 pairs
    #pragma unroll 4
    for (int p = 0; p < 16; p++) {
        int id0 = base + 2 * p;
        int id1 = id0 + 1;
        float a = 0.f, b = 0.f;
        if (id0 < n_nodes) a = (id0 < n_text) ? ent[id0 * EMB + tid] : nte[tid];
        if (id1 < n_nodes) b = (id1 < n_text) ? ent[id1 * EMB + tid] : nte[tid];
        he2[p][tid] = make_float2(a, b);
    }
    // load pe features (pair-packed): 160 (pair,j) slots
    for (int idx = tid; idx < 160; idx += EMB) {
        int p = idx / 10, j = idx % 10;
        int id0 = base + 2 * p;
        int id1 = id0 + 1;
        float a = 0.f, b = 0.f;
        if (j < 2) {
            if (id0 < n_nodes) a = ((const float*)topic)[id0 * 2 + j];
            if (id1 < n_nodes) b = ((const float*)topic)[id1 * 2 + j];
        } else {
            int rr = (j - 2) >> 1;
            if (id0 < n_nodes) { float2 d = g_d[rr][id0]; a = (j & 1) ? d.y : d.x; }
            if (id1 < n_nodes) { float2 d = g_d[rr][id1]; b = (j & 1) ? d.y : d.x; }
        }
        pe2[p][j] = make_float2(a, b);
    }
    __syncthreads();

    unsigned long long accA[16], accB[16];
    #pragma unroll
    for (int p = 0; p < 16; p++) { accA[p] = 0ULL; accB[p] = 0ULL; }

    #pragma unroll 2
    for (int k = 0; k < EMB; k++) {
        float wa = g_WThA[k * EMB + tid];
        float wb = g_WThB[k * EMB + tid];
        unsigned long long wa2 = pack2(wa, wa);
        unsigned long long wb2 = pack2(wb, wb);
        #pragma unroll
        for (int p = 0; p < 16; p++) {
            unsigned long long h = *(const unsigned long long*)&he2[p][k];
            ffma2(accA[p], h, wa2);
            ffma2(accB[p], h, wb2);
        }
    }
    #pragma unroll
    for (int j = 0; j < 10; j++) {
        float wa = g_WTpA[j * EMB + tid];
        float wb = g_WTpB[j * EMB + tid];
        unsigned long long wa2 = pack2(wa, wa);
        unsigned long long wb2 = pack2(wb, wb);
        #pragma unroll
        for (int p = 0; p < 16; p++) {
            unsigned long long v = *(const unsigned long long*)&pe2[p][j];
            ffma2(accA[p], v, wa2);
            ffma2(accB[p], v, wb2);
        }
    }
    #pragma unroll
    for (int p = 0; p < 16; p++) {
        int id0 = base + 2 * p;
        int id1 = id0 + 1;
        float alo, ahi, blo, bhi;
        unpack2(accA[p], alo, ahi);
        unpack2(accB[p], blo, bhi);
        if (id0 < n_nodes) { g_A[id0 * EMB + tid] = alo; g_B[id0 * EMB + tid] = blo; }
        if (id1 < n_nodes) { g_A[id1 * EMB + tid] = ahi; g_B[id1 * EMB + tid] = bhi; }
    }
}

// Edge combine: warp per edge. pred[e] = b2 + W2 . relu(A[h] + Rm[r] + B[t])
__global__ __launch_bounds__(256) void k_edge(
    const int* __restrict__ h_id, const int* __restrict__ r_id, const int* __restrict__ t_id,
    const float* __restrict__ W2, const float* __restrict__ b2,
    float* __restrict__ out, int E) {
    int gw = (blockIdx.x * blockDim.x + threadIdx.x) >> 5;
    int lane = threadIdx.x & 31;
    if (gw >= E) return;
    int h = h_id[gw];
    int t = t_id[gw];
    int r = r_id[gw];
    const float4* A4 = (const float4*)g_A;
    const float4* B4 = (const float4*)g_B;
    const float4* R4 = (const float4*)g_Rm;
    float4 a = A4[h * 32 + lane];
    float4 b = B4[t * 32 + lane];
    float4 c = R4[r * 32 + lane];
    float4 w = ((const float4*)W2)[lane];
    float s = w.x * fmaxf(a.x + b.x + c.x, 0.f)
            + w.y * fmaxf(a.y + b.y + c.y, 0.f)
            + w.z * fmaxf(a.z + b.z + c.z, 0.f)
            + w.w * fmaxf(a.w + b.w + c.w, 0.f);
    #pragma unroll
    for (int off = 16; off; off >>= 1) s += __shfl_xor_sync(0xFFFFFFFFu, s, off);
    if (lane == 0) out[gw] = s + b2[0];
}

// ---------------- launch ----------------

extern "C" void kernel_launch(void* const* d_in, const int* in_sizes, int n_in,
                              void* d_out, int out_size) {
    const int*   h_id  = (const int*)d_in[0];
    const int*   r_id  = (const int*)d_in[1];
    const int*   t_id  = (const int*)d_in[2];
    const float* q     = (const float*)d_in[3];
    const float* ent   = (const float*)d_in[4];
    const float* rel   = (const float*)d_in[6];
    const float* topic = (const float*)d_in[7];
    const float* nte   = (const float*)d_in[8];
    const float* W1    = (const float*)d_in[9];
    const float* b1    = (const float*)d_in[10];
    const float* W2    = (const float*)d_in[11];
    const float* b2    = (const float*)d_in[12];
    float* out = (float*)d_out;

    int E       = in_sizes[0];
    int n_text  = in_sizes[4] / EMB;
    int n_rel   = in_sizes[6] / EMB;
    int n_nodes = in_sizes[7] / 2;

    const int T = 256;
    int nb_nodes = (n_nodes + T - 1) / T;
    int nb_edges = (E + T - 1) / T;

    k_init<<<nb_nodes, T>>>(n_nodes);
    k_prep<<<(EMB * EMB + T - 1) / T, T>>>(W1);
    k_rm<<<(n_rel + RPB - 1) / RPB, EMB>>>(q, rel, b1, n_rel);

    const float2* topic2 = (const float2*)topic;
    k_sc1<<<nb_edges, T>>>(topic2, h_id, t_id, E);
    k_norm2d<<<nb_nodes, T>>>(0, 2, n_nodes);
    k_sc2<<<nb_edges, T>>>(h_id, t_id, E);
    k_norm2d<<<nb_nodes, T>>>(1, 3, n_nodes);

    k_tables<<<(n_nodes + NPB - 1) / NPB, EMB>>>(ent, nte, topic, n_text, n_nodes);

    int nb_e = (E + 7) / 8;
    k_edge<<<nb_e, T>>>(h_id, r_id, t_id, W2, b2, out, E);
}

// round 4
// speedup vs baseline: 1.3056x; 1.1844x over previous
#include <cuda_runtime.h>
#include <cuda_fp16.h>
#include <cuda_bf16.h>
#include <cstdint>

#define EMB 128
#define PRED_IN 532
#define MAX_NODES 131072
#define MAX_REL 1024
#define NPB 32    // nodes per block in table kernel (16 float2 pairs)
#define RPB 8     // relations per block in k_rm

// ---------------- scratch (static device globals; no allocation) ----------------
__device__ __align__(16) __half g_Ah[MAX_NODES * EMB];    // fp16 node table A
__device__ __align__(16) __half g_Bh[MAX_NODES * EMB];    // fp16 node table B
__device__ __align__(16) float g_Rm[MAX_REL * EMB];       // fp32 (L1-resident at edge time)
__device__ __align__(16) float g_WTq[EMB * EMB];          // [k][i] = W1[i][k]
__device__ __align__(16) float g_WThA[EMB * EMB];         // [k][i] = W1[i][128+k]
__device__ __align__(16) float g_WTr[EMB * EMB];          // [k][i] = W1[i][266+k]
__device__ __align__(16) float g_WThB[EMB * EMB];         // [k][i] = W1[i][394+k]
__device__ __align__(16) float g_WTpA[10 * EMB];          // [j][i] = W1[i][256+j]
__device__ __align__(16) float g_WTpB[10 * EMB];          // [j][i] = W1[i][522+j]
__device__ __align__(16) float4 g_scrf[MAX_NODES];        // {sum.x, sum.y, deg_t, pad}
__device__ __align__(16) float4 g_scrr[MAX_NODES];        // {sum.x, sum.y, deg_h, pad}
__device__ __align__(16) float2 g_d[4][MAX_NODES];        // d0,d1 fwd; d2,d3 rev

// ---------------- f32x2 helpers ----------------
__device__ __forceinline__ unsigned long long pack2(float a, float b) {
    unsigned long long r;
    asm("mov.b64 %0, {%1, %2};" : "=l"(r) : "f"(a), "f"(b));
    return r;
}
__device__ __forceinline__ void unpack2(unsigned long long v, float& lo, float& hi) {
    asm("mov.b64 {%0, %1}, %2;" : "=f"(lo), "=f"(hi) : "l"(v));
}
__device__ __forceinline__ void ffma2(unsigned long long& acc, unsigned long long a,
                                      unsigned long long b) {
    asm("fma.rn.f32x2 %0, %1, %2, %0;" : "+l"(acc) : "l"(a), "l"(b));
}

// ---------------- kernels ----------------

__global__ void k_init(int n_nodes) {
    int i = blockIdx.x * blockDim.x + threadIdx.x;
    if (i < n_nodes) {
        g_scrf[i] = make_float4(0.f, 0.f, 0.f, 0.f);
        g_scrr[i] = make_float4(0.f, 0.f, 0.f, 0.f);
    }
}

__global__ void k_prep(const float* __restrict__ W1) {
    int idx = blockIdx.x * blockDim.x + threadIdx.x;
    if (idx < EMB * EMB) {
        int k = idx >> 7;
        int i = idx & 127;
        const float* row = W1 + i * PRED_IN;
        g_WTq[idx]  = row[k];
        g_WThA[idx] = row[128 + k];
        g_WTr[idx]  = row[266 + k];
        g_WThB[idx] = row[394 + k];
    }
    if (idx < 10 * EMB) {
        int j = idx >> 7;
        int i = idx & 127;
        const float* row = W1 + i * PRED_IN;
        g_WTpA[idx] = row[256 + j];
        g_WTpB[idx] = row[522 + j];
    }
}

// Rm[r][i] = b1[i] + dot(W1[i,0:128], q) + dot(W1[i,266:394], rel[r]); RPB rels/block
__global__ __launch_bounds__(EMB) void k_rm(const float* __restrict__ q,
                                            const float* __restrict__ rel,
                                            const float* __restrict__ b1, int n_rel) {
    __shared__ float qs[EMB];
    __shared__ float rs[RPB][EMB];
    int i = threadIdx.x;
    int rbase = blockIdx.x * RPB;
    qs[i] = q[i];
    #pragma unroll
    for (int r = 0; r < RPB; r++) {
        int rid = rbase + r;
        rs[r][i] = (rid < n_rel) ? rel[rid * EMB + i] : 0.f;
    }
    __syncthreads();
    float accq = b1[i];
    float acc[RPB];
    #pragma unroll
    for (int r = 0; r < RPB; r++) acc[r] = 0.f;
    #pragma unroll 4
    for (int k = 0; k < EMB; k++) {
        float wq = g_WTq[k * EMB + i];
        float wr = g_WTr[k * EMB + i];
        accq += wq * qs[k];
        #pragma unroll
        for (int r = 0; r < RPB; r++) acc[r] += wr * rs[r][k];
    }
    #pragma unroll
    for (int r = 0; r < RPB; r++) {
        int rid = rbase + r;
        if (rid < n_rel) g_Rm[rid * EMB + i] = accq + acc[r];
    }
}

// Round 1 fused: degrees + fwd scatter (topic[h]->t) + rev scatter (topic[t]->h)
// One red.v4 per direction: {pe.x, pe.y, +1 degree, 0}
__global__ void k_sc1(const float2* __restrict__ topic, const int* __restrict__ h_id,
                      const int* __restrict__ t_id, int E) {
    int e = blockIdx.x * blockDim.x + threadIdx.x;
    if (e < E) {
        int h = h_id[e];
        int t = t_id[e];
        float2 vh = topic[h];
        float2 vt = topic[t];
        float4* pf = &g_scrf[t];
        float4* pr = &g_scrr[h];
        asm volatile("red.global.add.v4.f32 [%0], {%1, %2, %3, %4};"
                     :: "l"(pf), "f"(vh.x), "f"(vh.y), "f"(1.f), "f"(0.f) : "memory");
        asm volatile("red.global.add.v4.f32 [%0], {%1, %2, %3, %4};"
                     :: "l"(pr), "f"(vt.x), "f"(vt.y), "f"(1.f), "f"(0.f) : "memory");
    }
}

// normalize both directions into g_d[fo]/g_d[ro]; reset xy (keep degree) if !last
__global__ void k_norm2d(int fo, int ro, int last, int n_nodes) {
    int i = blockIdx.x * blockDim.x + threadIdx.x;
    if (i < n_nodes) {
        float4 sf = g_scrf[i];
        float4 sr = g_scrr[i];
        float ct = fmaxf(sf.z, 1.f);
        float ch = fmaxf(sr.z, 1.f);
        g_d[fo][i] = make_float2(sf.x / ct, sf.y / ct);
        g_d[ro][i] = make_float2(sr.x / ch, sr.y / ch);
        if (!last) {
            g_scrf[i] = make_float4(0.f, 0.f, sf.z, 0.f);
            g_scrr[i] = make_float4(0.f, 0.f, sr.z, 0.f);
        }
    }
}

// Round 2 fused: fwd scatter (d0[h]->t) + rev scatter (d2[t]->h)
__global__ void k_sc2(const int* __restrict__ h_id, const int* __restrict__ t_id, int E) {
    int e = blockIdx.x * blockDim.x + threadIdx.x;
    if (e < E) {
        int h = h_id[e];
        int t = t_id[e];
        float2 vh = g_d[0][h];
        float2 vt = g_d[2][t];
        float* pf = &g_scrf[t].x;
        float* pr = &g_scrr[h].x;
        asm volatile("red.global.add.v2.f32 [%0], {%1, %2};"
                     :: "l"(pf), "f"(vh.x), "f"(vh.y) : "memory");
        asm volatile("red.global.add.v2.f32 [%0], {%1, %2};"
                     :: "l"(pr), "f"(vt.x), "f"(vt.y) : "memory");
    }
}

// Node tables via packed f32x2: 32 nodes (16 pairs) per 128-thread block.
// Non-text blocks (base >= n_text): h_e part is a per-dim constant -> 10-MAC path.
__global__ __launch_bounds__(EMB) void k_tables(
    const float* __restrict__ ent, const float* __restrict__ nte,
    const float* __restrict__ topic, int n_text, int n_nodes) {
    __shared__ float2 he2[16][EMB];   // [pair][k]
    __shared__ float2 pe2[16][10];    // [pair][j]
    int tid = threadIdx.x;
    int base = blockIdx.x * NPB;
    bool all_nontext = (base >= n_text);

    // pe features (both paths need them)
    for (int idx = tid; idx < 160; idx += EMB) {
        int p = idx / 10, j = idx % 10;
        int id0 = base + 2 * p;
        int id1 = id0 + 1;
        float a = 0.f, b = 0.f;
        if (j < 2) {
            if (id0 < n_nodes) a = topic[id0 * 2 + j];
            if (id1 < n_nodes) b = topic[id1 * 2 + j];
        } else {
            int rr = (j - 2) >> 1;
            if (id0 < n_nodes) { float2 d = g_d[rr][id0]; a = (j & 1) ? d.y : d.x; }
            if (id1 < n_nodes) { float2 d = g_d[rr][id1]; b = (j & 1) ? d.y : d.x; }
        }
        pe2[p][j] = make_float2(a, b);
    }

    unsigned long long accA[16], accB[16];

    if (all_nontext) {
        // constant h_e = nte for every node in this block
        __shared__ float nts[EMB];
        nts[tid] = nte[tid];
        __syncthreads();
        float cA = 0.f, cB = 0.f;
        #pragma unroll 4
        for (int k = 0; k < EMB; k++) {
            float nv = nts[k];
            cA += g_WThA[k * EMB + tid] * nv;
            cB += g_WThB[k * EMB + tid] * nv;
        }
        unsigned long long cA2 = pack2(cA, cA);
        unsigned long long cB2 = pack2(cB, cB);
        #pragma unroll
        for (int p = 0; p < 16; p++) { accA[p] = cA2; accB[p] = cB2; }
    } else {
        #pragma unroll 4
        for (int p = 0; p < 16; p++) {
            int id0 = base + 2 * p;
            int id1 = id0 + 1;
            float a = 0.f, b = 0.f;
            if (id0 < n_nodes) a = (id0 < n_text) ? ent[id0 * EMB + tid] : nte[tid];
            if (id1 < n_nodes) b = (id1 < n_text) ? ent[id1 * EMB + tid] : nte[tid];
            he2[p][tid] = make_float2(a, b);
        }
        __syncthreads();
        #pragma unroll
        for (int p = 0; p < 16; p++) { accA[p] = 0ULL; accB[p] = 0ULL; }
        #pragma unroll 2
        for (int k = 0; k < EMB; k++) {
            float wa = g_WThA[k * EMB + tid];
            float wb = g_WThB[k * EMB + tid];
            unsigned long long wa2 = pack2(wa, wa);
            unsigned long long wb2 = pack2(wb, wb);
            #pragma unroll
            for (int p = 0; p < 16; p++) {
                unsigned long long h = *(const unsigned long long*)&he2[p][k];
                ffma2(accA[p], h, wa2);
                ffma2(accB[p], h, wb2);
            }
        }
    }
    if (all_nontext) __syncthreads();   // pe2 ready (written before any sync in this path)

    #pragma unroll
    for (int j = 0; j < 10; j++) {
        float wa = g_WTpA[j * EMB + tid];
        float wb = g_WTpB[j * EMB + tid];
        unsigned long long wa2 = pack2(wa, wa);
        unsigned long long wb2 = pack2(wb, wb);
        #pragma unroll
        for (int p = 0; p < 16; p++) {
            unsigned long long v = *(const unsigned long long*)&pe2[p][j];
            ffma2(accA[p], v, wa2);
            ffma2(accB[p], v, wb2);
        }
    }
    #pragma unroll
    for (int p = 0; p < 16; p++) {
        int id0 = base + 2 * p;
        int id1 = id0 + 1;
        float alo, ahi, blo, bhi;
        unpack2(accA[p], alo, ahi);
        unpack2(accB[p], blo, bhi);
        if (id0 < n_nodes) {
            g_Ah[id0 * EMB + tid] = __float2half_rn(alo);
            g_Bh[id0 * EMB + tid] = __float2half_rn(blo);
        }
        if (id1 < n_nodes) {
            g_Ah[id1 * EMB + tid] = __float2half_rn(ahi);
            g_Bh[id1 * EMB + tid] = __float2half_rn(bhi);
        }
    }
}

// Edge combine: warp per edge. pred[e] = b2 + W2 . relu(A[h] + Rm[r] + B[t])
// A/B fp16 (8B per lane = 4 dims), Rm/W2 fp32.
__global__ __launch_bounds__(256) void k_edge(
    const int* __restrict__ h_id, const int* __restrict__ r_id, const int* __restrict__ t_id,
    const float* __restrict__ W2, const float* __restrict__ b2,
    float* __restrict__ out, int E) {
    int gw = (blockIdx.x * blockDim.x + threadIdx.x) >> 5;
    int lane = threadIdx.x & 31;
    if (gw >= E) return;
    int h = h_id[gw];
    int t = t_id[gw];
    int r = r_id[gw];
    const uint2* A2 = (const uint2*)g_Ah;   // 4 halfs per lane
    const uint2* B2 = (const uint2*)g_Bh;
    const float4* R4 = (const float4*)g_Rm;
    uint2 ua = A2[h * 32 + lane];
    uint2 ub = B2[t * 32 + lane];
    float4 c = R4[r * 32 + lane];
    float4 w = ((const float4*)W2)[lane];
    float2 a01 = __half22float2(*(const __half2*)&ua.x);
    float2 a23 = __half22float2(*(const __half2*)&ua.y);
    float2 b01 = __half22float2(*(const __half2*)&ub.x);
    float2 b23 = __half22float2(*(const __half2*)&ub.y);
    float s = w.x * fmaxf(a01.x + b01.x + c.x, 0.f)
            + w.y * fmaxf(a01.y + b01.y + c.y, 0.f)
            + w.z * fmaxf(a23.x + b23.x + c.z, 0.f)
            + w.w * fmaxf(a23.y + b23.y + c.w, 0.f);
    #pragma unroll
    for (int off = 16; off; off >>= 1) s += __shfl_xor_sync(0xFFFFFFFFu, s, off);
    if (lane == 0) out[gw] = s + b2[0];
}

// ---------------- launch ----------------

extern "C" void kernel_launch(void* const* d_in, const int* in_sizes, int n_in,
                              void* d_out, int out_size) {
    const int*   h_id  = (const int*)d_in[0];
    const int*   r_id  = (const int*)d_in[1];
    const int*   t_id  = (const int*)d_in[2];
    const float* q     = (const float*)d_in[3];
    const float* ent   = (const float*)d_in[4];
    const float* rel   = (const float*)d_in[6];
    const float* topic = (const float*)d_in[7];
    const float* nte   = (const float*)d_in[8];
    const float* W1    = (const float*)d_in[9];
    const float* b1    = (const float*)d_in[10];
    const float* W2    = (const float*)d_in[11];
    const float* b2    = (const float*)d_in[12];
    float* out = (float*)d_out;

    int E       = in_sizes[0];
    int n_text  = in_sizes[4] / EMB;
    int n_rel   = in_sizes[6] / EMB;
    int n_nodes = in_sizes[7] / 2;

    const int T = 256;
    int nb_nodes = (n_nodes + T - 1) / T;
    int nb_edges = (E + T - 1) / T;

    k_init<<<nb_nodes, T>>>(n_nodes);
    k_prep<<<(EMB * EMB + T - 1) / T, T>>>(W1);
    k_rm<<<(n_rel + RPB - 1) / RPB, EMB>>>(q, rel, b1, n_rel);

    const float2* topic2 = (const float2*)topic;
    k_sc1<<<nb_edges, T>>>(topic2, h_id, t_id, E);
    k_norm2d<<<nb_nodes, T>>>(0, 2, 0, n_nodes);
    k_sc2<<<nb_edges, T>>>(h_id, t_id, E);
    k_norm2d<<<nb_nodes, T>>>(1, 3, 1, n_nodes);

    k_tables<<<(n_nodes + NPB - 1) / NPB, EMB>>>(ent, nte, topic, n_text, n_nodes);

    int nb_e = (E + 7) / 8;
    k_edge<<<nb_e, T>>>(h_id, r_id, t_id, W2, b2, out, E);
}

// round 5
// speedup vs baseline: 1.3180x; 1.0095x over previous
#include <cuda_runtime.h>
#include <cuda_fp16.h>
#include <cuda_bf16.h>
#include <cstdint>

#define EMB 128
#define PRED_IN 532
#define MAX_NODES 131072
#define MAX_REL 1024
#define NPB 32    // nodes per block in table kernel (16 float2 pairs)
#define RPB 8     // relations per block in k_rm

// ---------------- scratch (static device globals; no allocation) ----------------
__device__ __align__(16) __half g_Ah[MAX_NODES * EMB];    // fp16 node table A
__device__ __align__(16) __half g_Bh[MAX_NODES * EMB];    // fp16 node table B
__device__ __align__(16) __half g_Rmh[MAX_REL * EMB];     // fp16 rel table (L1-resident: 128KB)
__device__ __align__(16) float g_WTq[EMB * EMB];          // [k][i] = W1[i][k]
__device__ __align__(16) float g_WThA[EMB * EMB];         // [k][i] = W1[i][128+k]
__device__ __align__(16) float g_WTr[EMB * EMB];          // [k][i] = W1[i][266+k]
__device__ __align__(16) float g_WThB[EMB * EMB];         // [k][i] = W1[i][394+k]
__device__ __align__(16) float g_WTpA[10 * EMB];          // [j][i] = W1[i][256+j]
__device__ __align__(16) float g_WTpB[10 * EMB];          // [j][i] = W1[i][522+j]
__device__ __align__(16) float4 g_scrf[MAX_NODES];        // {sum.x, sum.y, deg_t, pad}
__device__ __align__(16) float4 g_scrr[MAX_NODES];        // {sum.x, sum.y, deg_h, pad}
__device__ __align__(16) float2 g_d[4][MAX_NODES];        // d0,d1 fwd; d2,d3 rev

// ---------------- f32x2 helpers ----------------
__device__ __forceinline__ unsigned long long pack2(float a, float b) {
    unsigned long long r;
    asm("mov.b64 %0, {%1, %2};" : "=l"(r) : "f"(a), "f"(b));
    return r;
}
__device__ __forceinline__ void unpack2(unsigned long long v, float& lo, float& hi) {
    asm("mov.b64 {%0, %1}, %2;" : "=f"(lo), "=f"(hi) : "l"(v));
}
__device__ __forceinline__ void ffma2(unsigned long long& acc, unsigned long long a,
                                      unsigned long long b) {
    asm("fma.rn.f32x2 %0, %1, %2, %0;" : "+l"(acc) : "l"(a), "l"(b));
}

// ---------------- kernels ----------------

__global__ void k_init(int n_nodes) {
    int i = blockIdx.x * blockDim.x + threadIdx.x;
    if (i < n_nodes) {
        g_scrf[i] = make_float4(0.f, 0.f, 0.f, 0.f);
        g_scrr[i] = make_float4(0.f, 0.f, 0.f, 0.f);
    }
}

__global__ void k_prep(const float* __restrict__ W1) {
    int idx = blockIdx.x * blockDim.x + threadIdx.x;
    if (idx < EMB * EMB) {
        int k = idx >> 7;
        int i = idx & 127;
        const float* row = W1 + i * PRED_IN;
        g_WTq[idx]  = row[k];
        g_WThA[idx] = row[128 + k];
        g_WTr[idx]  = row[266 + k];
        g_WThB[idx] = row[394 + k];
    }
    if (idx < 10 * EMB) {
        int j = idx >> 7;
        int i = idx & 127;
        const float* row = W1 + i * PRED_IN;
        g_WTpA[idx] = row[256 + j];
        g_WTpB[idx] = row[522 + j];
    }
}

// Rm[r][i] = b1[i] + dot(W1[i,0:128], q) + dot(W1[i,266:394], rel[r]); RPB rels/block
// fp32 compute, fp16 store.
__global__ __launch_bounds__(EMB) void k_rm(const float* __restrict__ q,
                                            const float* __restrict__ rel,
                                            const float* __restrict__ b1, int n_rel) {
    __shared__ float qs[EMB];
    __shared__ float rs[RPB][EMB];
    int i = threadIdx.x;
    int rbase = blockIdx.x * RPB;
    qs[i] = q[i];
    #pragma unroll
    for (int r = 0; r < RPB; r++) {
        int rid = rbase + r;
        rs[r][i] = (rid < n_rel) ? rel[rid * EMB + i] : 0.f;
    }
    __syncthreads();
    float accq = b1[i];
    float acc[RPB];
    #pragma unroll
    for (int r = 0; r < RPB; r++) acc[r] = 0.f;
    #pragma unroll 4
    for (int k = 0; k < EMB; k++) {
        float wq = g_WTq[k * EMB + i];
        float wr = g_WTr[k * EMB + i];
        accq += wq * qs[k];
        #pragma unroll
        for (int r = 0; r < RPB; r++) acc[r] += wr * rs[r][k];
    }
    #pragma unroll
    for (int r = 0; r < RPB; r++) {
        int rid = rbase + r;
        if (rid < n_rel) g_Rmh[rid * EMB + i] = __float2half_rn(accq + acc[r]);
    }
}

// Round 1 fused: degrees + fwd scatter (topic[h]->t) + rev scatter (topic[t]->h)
__global__ void k_sc1(const float2* __restrict__ topic, const int* __restrict__ h_id,
                      const int* __restrict__ t_id, int E) {
    int e = blockIdx.x * blockDim.x + threadIdx.x;
    if (e < E) {
        int h = h_id[e];
        int t = t_id[e];
        float2 vh = topic[h];
        float2 vt = topic[t];
        float4* pf = &g_scrf[t];
        float4* pr = &g_scrr[h];
        asm volatile("red.global.add.v4.f32 [%0], {%1, %2, %3, %4};"
                     :: "l"(pf), "f"(vh.x), "f"(vh.y), "f"(1.f), "f"(0.f) : "memory");
        asm volatile("red.global.add.v4.f32 [%0], {%1, %2, %3, %4};"
                     :: "l"(pr), "f"(vt.x), "f"(vt.y), "f"(1.f), "f"(0.f) : "memory");
    }
}

// normalize both directions into g_d[fo]/g_d[ro]; reset xy (keep degree) if !last
__global__ void k_norm2d(int fo, int ro, int last, int n_nodes) {
    int i = blockIdx.x * blockDim.x + threadIdx.x;
    if (i < n_nodes) {
        float4 sf = g_scrf[i];
        float4 sr = g_scrr[i];
        float ct = fmaxf(sf.z, 1.f);
        float ch = fmaxf(sr.z, 1.f);
        g_d[fo][i] = make_float2(sf.x / ct, sf.y / ct);
        g_d[ro][i] = make_float2(sr.x / ch, sr.y / ch);
        if (!last) {
            g_scrf[i] = make_float4(0.f, 0.f, sf.z, 0.f);
            g_scrr[i] = make_float4(0.f, 0.f, sr.z, 0.f);
        }
    }
}

// Round 2 fused: fwd scatter (d0[h]->t) + rev scatter (d2[t]->h)
__global__ void k_sc2(const int* __restrict__ h_id, const int* __restrict__ t_id, int E) {
    int e = blockIdx.x * blockDim.x + threadIdx.x;
    if (e < E) {
        int h = h_id[e];
        int t = t_id[e];
        float2 vh = g_d[0][h];
        float2 vt = g_d[2][t];
        float* pf = &g_scrf[t].x;
        float* pr = &g_scrr[h].x;
        asm volatile("red.global.add.v2.f32 [%0], {%1, %2};"
                     :: "l"(pf), "f"(vh.x), "f"(vh.y) : "memory");
        asm volatile("red.global.add.v2.f32 [%0], {%1, %2};"
                     :: "l"(pr), "f"(vt.x), "f"(vt.y) : "memory");
    }
}

// Node tables via packed f32x2: 32 nodes (16 pairs) per 128-thread block.
// Non-text blocks (base >= n_text): h_e part is a per-dim constant -> 10-MAC path.
__global__ __launch_bounds__(EMB) void k_tables(
    const float* __restrict__ ent, const float* __restrict__ nte,
    const float* __restrict__ topic, int n_text, int n_nodes) {
    __shared__ float2 he2[16][EMB];   // [pair][k]
    __shared__ float2 pe2[16][10];    // [pair][j]
    int tid = threadIdx.x;
    int base = blockIdx.x * NPB;
    bool all_nontext = (base >= n_text);

    // pe features (both paths need them)
    for (int idx = tid; idx < 160; idx += EMB) {
        int p = idx / 10, j = idx % 10;
        int id0 = base + 2 * p;
        int id1 = id0 + 1;
        float a = 0.f, b = 0.f;
        if (j < 2) {
            if (id0 < n_nodes) a = topic[id0 * 2 + j];
            if (id1 < n_nodes) b = topic[id1 * 2 + j];
        } else {
            int rr = (j - 2) >> 1;
            if (id0 < n_nodes) { float2 d = g_d[rr][id0]; a = (j & 1) ? d.y : d.x; }
            if (id1 < n_nodes) { float2 d = g_d[rr][id1]; b = (j & 1) ? d.y : d.x; }
        }
        pe2[p][j] = make_float2(a, b);
    }

    unsigned long long accA[16], accB[16];

    if (all_nontext) {
        __shared__ float nts[EMB];
        nts[tid] = nte[tid];
        __syncthreads();
        float cA = 0.f, cB = 0.f;
        #pragma unroll 4
        for (int k = 0; k < EMB; k++) {
            float nv = nts[k];
            cA += g_WThA[k * EMB + tid] * nv;
            cB += g_WThB[k * EMB + tid] * nv;
        }
        unsigned long long cA2 = pack2(cA, cA);
        unsigned long long cB2 = pack2(cB, cB);
        #pragma unroll
        for (int p = 0; p < 16; p++) { accA[p] = cA2; accB[p] = cB2; }
    } else {
        #pragma unroll 4
        for (int p = 0; p < 16; p++) {
            int id0 = base + 2 * p;
            int id1 = id0 + 1;
            float a = 0.f, b = 0.f;
            if (id0 < n_nodes) a = (id0 < n_text) ? ent[id0 * EMB + tid] : nte[tid];
            if (id1 < n_nodes) b = (id1 < n_text) ? ent[id1 * EMB + tid] : nte[tid];
            he2[p][tid] = make_float2(a, b);
        }
        __syncthreads();
        #pragma unroll
        for (int p = 0; p < 16; p++) { accA[p] = 0ULL; accB[p] = 0ULL; }
        #pragma unroll 2
        for (int k = 0; k < EMB; k++) {
            float wa = g_WThA[k * EMB + tid];
            float wb = g_WThB[k * EMB + tid];
            unsigned long long wa2 = pack2(wa, wa);
            unsigned long long wb2 = pack2(wb, wb);
            #pragma unroll
            for (int p = 0; p < 16; p++) {
                unsigned long long h = *(const unsigned long long*)&he2[p][k];
                ffma2(accA[p], h, wa2);
                ffma2(accB[p], h, wb2);
            }
        }
    }
    if (all_nontext) __syncthreads();

    #pragma unroll
    for (int j = 0; j < 10; j++) {
        float wa = g_WTpA[j * EMB + tid];
        float wb = g_WTpB[j * EMB + tid];
        unsigned long long wa2 = pack2(wa, wa);
        unsigned long long wb2 = pack2(wb, wb);
        #pragma unroll
        for (int p = 0; p < 16; p++) {
            unsigned long long v = *(const unsigned long long*)&pe2[p][j];
            ffma2(accA[p], v, wa2);
            ffma2(accB[p], v, wb2);
        }
    }
    #pragma unroll
    for (int p = 0; p < 16; p++) {
        int id0 = base + 2 * p;
        int id1 = id0 + 1;
        float alo, ahi, blo, bhi;
        unpack2(accA[p], alo, ahi);
        unpack2(accB[p], blo, bhi);
        if (id0 < n_nodes) {
            g_Ah[id0 * EMB + tid] = __float2half_rn(alo);
            g_Bh[id0 * EMB + tid] = __float2half_rn(blo);
        }
        if (id1 < n_nodes) {
            g_Ah[id1 * EMB + tid] = __float2half_rn(ahi);
            g_Bh[id1 * EMB + tid] = __float2half_rn(bhi);
        }
    }
}

// Edge combine: warp per edge. pred[e] = b2 + W2 . relu(A[h] + Rm[r] + B[t])
// A/B/Rm fp16 (8B per lane = 4 dims), W2 fp32, compute fp32.
__global__ __launch_bounds__(256) void k_edge(
    const int* __restrict__ h_id, const int* __restrict__ r_id, const int* __restrict__ t_id,
    const float* __restrict__ W2, const float* __restrict__ b2,
    float* __restrict__ out, int E) {
    int gw = (blockIdx.x * blockDim.x + threadIdx.x) >> 5;
    int lane = threadIdx.x & 31;
    if (gw >= E) return;
    int h = h_id[gw];
    int t = t_id[gw];
    int r = r_id[gw];
    const uint2* A2 = (const uint2*)g_Ah;
    const uint2* B2 = (const uint2*)g_Bh;
    const uint2* R2 = (const uint2*)g_Rmh;
    uint2 ua = A2[h * 32 + lane];
    uint2 ub = B2[t * 32 + lane];
    uint2 uc = R2[r * 32 + lane];
    float4 w = ((const float4*)W2)[lane];
    float2 a01 = __half22float2(*(const __half2*)&ua.x);
    float2 a23 = __half22float2(*(const __half2*)&ua.y);
    float2 b01 = __half22float2(*(const __half2*)&ub.x);
    float2 b23 = __half22float2(*(const __half2*)&ub.y);
    float2 c01 = __half22float2(*(const __half2*)&uc.x);
    float2 c23 = __half22float2(*(const __half2*)&uc.y);
    float s = w.x * fmaxf(a01.x + b01.x + c01.x, 0.f)
            + w.y * fmaxf(a01.y + b01.y + c01.y, 0.f)
            + w.z * fmaxf(a23.x + b23.x + c23.x, 0.f)
            + w.w * fmaxf(a23.y + b23.y + c23.y, 0.f);
    #pragma unroll
    for (int off = 16; off; off >>= 1) s += __shfl_xor_sync(0xFFFFFFFFu, s, off);
    if (lane == 0) out[gw] = s + b2[0];
}

// ---------------- launch ----------------

extern "C" void kernel_launch(void* const* d_in, const int* in_sizes, int n_in,
                              void* d_out, int out_size) {
    const int*   h_id  = (const int*)d_in[0];
    const int*   r_id  = (const int*)d_in[1];
    const int*   t_id  = (const int*)d_in[2];
    const float* q     = (const float*)d_in[3];
    const float* ent   = (const float*)d_in[4];
    const float* rel   = (const float*)d_in[6];
    const float* topic = (const float*)d_in[7];
    const float* nte   = (const float*)d_in[8];
    const float* W1    = (const float*)d_in[9];
    const float* b1    = (const float*)d_in[10];
    const float* W2    = (const float*)d_in[11];
    const float* b2    = (const float*)d_in[12];
    float* out = (float*)d_out;

    int E       = in_sizes[0];
    int n_text  = in_sizes[4] / EMB;
    int n_rel   = in_sizes[6] / EMB;
    int n_nodes = in_sizes[7] / 2;

    const int T = 256;
    int nb_nodes = (n_nodes + T - 1) / T;
    int nb_edges = (E + T - 1) / T;

    k_init<<<nb_nodes, T>>>(n_nodes);
    k_prep<<<(EMB * EMB + T - 1) / T, T>>>(W1);
    k_rm<<<(n_rel + RPB - 1) / RPB, EMB>>>(q, rel, b1, n_rel);

    const float2* topic2 = (const float2*)topic;
    k_sc1<<<nb_edges, T>>>(topic2, h_id, t_id, E);
    k_norm2d<<<nb_nodes, T>>>(0, 2, 0, n_nodes);
    k_sc2<<<nb_edges, T>>>(h_id, t_id, E);
    k_norm2d<<<nb_nodes, T>>>(1, 3, 1, n_nodes);

    k_tables<<<(n_nodes + NPB - 1) / NPB, EMB>>>(ent, nte, topic, n_text, n_nodes);

    int nb_e = (E + 7) / 8;
    k_edge<<<nb_e, T>>>(h_id, r_id, t_id, W2, b2, out, E);
}